// round 2
// baseline (speedup 1.0000x reference)
#include <cuda_runtime.h>
#include <math.h>

#define BB 8
#define NN 4096
#define CC 96
#define C2 192
#define NP 1024
#define NSAMP 16
#define FULLMASK 0xffffffffu
#define KC 32

// ---------------- scratch ----------------
__device__ int   d_samp[BB*NP];
__device__ int   d_nbr[BB*NP*NSAMP];
__device__ float d_Bfeat[BB*NN*C2];    // [b][n][c]  = scale_t*(Wt[:,96:]@relu(x)) + shift_t
__device__ float d_Afeat[BB*NP*C2];    // [b][g][c]  = scale_t*(Wt[:,:96]@relu(x_samp))
__device__ float d_Pool[BB*NP*C2];     // [b][g][c]  = relu(max+mean pooled)
__device__ float d_WtT[C2*C2];         // [c][o]
__device__ float d_WcT[C2*C2];         // [c][o]
__device__ float d_scale_t[C2], d_shift_t[C2], d_scale_c[C2], d_shift_c[C2];

// ---------------- prep: transpose weights, fold BN ----------------
__global__ void prep_kernel(const float* __restrict__ Wt, const float* __restrict__ gt,
                            const float* __restrict__ bt, const float* __restrict__ mt,
                            const float* __restrict__ vt, const float* __restrict__ Wc,
                            const float* __restrict__ gc, const float* __restrict__ bc,
                            const float* __restrict__ mc, const float* __restrict__ vc) {
    int tid = threadIdx.x + blockIdx.x * blockDim.x;
    int stride = blockDim.x * gridDim.x;
    for (int i = tid; i < C2*C2; i += stride) {
        int o = i / C2, c = i % C2;
        d_WtT[c*C2 + o] = Wt[o*C2 + c];
        d_WcT[c*C2 + o] = Wc[o*C2 + c];
    }
    if (blockIdx.x == 0 && threadIdx.x < C2) {
        int i = threadIdx.x;
        float st = gt[i] / sqrtf(vt[i] + 1e-5f);
        d_scale_t[i] = st;
        d_shift_t[i] = bt[i] - mt[i]*st;
        float sc = gc[i] / sqrtf(vc[i] + 1e-5f);
        d_scale_c[i] = sc;
        d_shift_c[i] = bc[i] - mc[i]*sc;
    }
}

// ---------------- FPS: one block per batch, bit-exact vs reference ----------------
__global__ __launch_bounds__(1024, 1) void fps_kernel(const float* __restrict__ p,
                                                      float* __restrict__ newp) {
    int b = blockIdx.x;
    const float* pb = p + (size_t)b * NN * 3;
    int tid = threadIdx.x, lane = tid & 31, warp = tid >> 5;

    float px[4], py[4], pz[4], mind[4];
    int base = tid * 4;
    #pragma unroll
    for (int i = 0; i < 4; i++) {
        px[i] = pb[(base+i)*3 + 0];
        py[i] = pb[(base+i)*3 + 1];
        pz[i] = pb[(base+i)*3 + 2];
        mind[i] = 1e10f;
    }

    __shared__ float ls[3];
    __shared__ float redv[32];
    __shared__ int   redi[32];
    __shared__ float smaxv;
    __shared__ int   scur;
    if (tid == 0) { ls[0] = pb[0]; ls[1] = pb[1]; ls[2] = pb[2]; scur = 0; }
    __syncthreads();

    for (int k = 0; k < NP; k++) {
        if (tid == 0) {
            d_samp[b*NP + k] = scur;
            newp[(b*NP + k)*3 + 0] = ls[0];
            newp[(b*NP + k)*3 + 1] = ls[1];
            newp[(b*NP + k)*3 + 2] = ls[2];
        }
        if (k == NP-1) break;

        float lx = ls[0], ly = ls[1], lz = ls[2];
        #pragma unroll
        for (int i = 0; i < 4; i++) {
            float dx = __fsub_rn(px[i], lx);
            float dy = __fsub_rn(py[i], ly);
            float dz = __fsub_rn(pz[i], lz);
            float d  = __fadd_rn(__fadd_rn(__fmul_rn(dx,dx), __fmul_rn(dy,dy)), __fmul_rn(dz,dz));
            mind[i] = fminf(mind[i], d);
        }
        float bmax = fmaxf(fmaxf(mind[0], mind[1]), fmaxf(mind[2], mind[3]));
        #pragma unroll
        for (int o = 16; o; o >>= 1) bmax = fmaxf(bmax, __shfl_xor_sync(FULLMASK, bmax, o));
        if (lane == 0) redv[warp] = bmax;
        __syncthreads();
        if (warp == 0) {
            float v = redv[lane];
            #pragma unroll
            for (int o = 16; o; o >>= 1) v = fmaxf(v, __shfl_xor_sync(FULLMASK, v, o));
            if (lane == 0) smaxv = v;
        }
        __syncthreads();
        float mv = smaxv;
        int loc = 0x7fffffff;
        #pragma unroll
        for (int i = 3; i >= 0; i--) if (mind[i] == mv) loc = base + i;   // keep smallest idx
        #pragma unroll
        for (int o = 16; o; o >>= 1) loc = min(loc, __shfl_xor_sync(FULLMASK, loc, o));
        if (lane == 0) redi[warp] = loc;
        __syncthreads();
        if (warp == 0) {
            int v = redi[lane];
            #pragma unroll
            for (int o = 16; o; o >>= 1) v = min(v, __shfl_xor_sync(FULLMASK, v, o));
            if (lane == 0) {
                scur = v;
                ls[0] = pb[v*3+0]; ls[1] = pb[v*3+1]; ls[2] = pb[v*3+2];
            }
        }
        __syncthreads();
    }
}

// ---------------- ball query: 16 warps/block, one warp per center ----------------
__global__ __launch_bounds__(512) void ballq_kernel(const float* __restrict__ p) {
    __shared__ float sx[NN], sy[NN], sz[NN];
    int b   = blockIdx.x >> 6;       // 64 groups per batch
    int grp = blockIdx.x & 63;
    const float* pb = p + (size_t)b * NN * 3;
    for (int i = threadIdx.x; i < NN; i += 512) {
        sx[i] = pb[3*i + 0];
        sy[i] = pb[3*i + 1];
        sz[i] = pb[3*i + 2];
    }
    __syncthreads();

    int warp = threadIdx.x >> 5, lane = threadIdx.x & 31;
    int g = grp*16 + warp;
    int cIdx = d_samp[b*NP + g];
    float cx = sx[cIdx], cy = sy[cIdx], cz = sz[cIdx];
    const float R2 = (float)(0.1 * 0.1);   // matches reference's f64->f32 rounding
    int* outp = d_nbr + ((size_t)(b*NP + g)) * NSAMP;

    int cnt = 0;
    int fi = 0;
    for (int basei = 0; basei < NN && cnt < NSAMP; basei += 32) {
        int i = basei + lane;
        float dx = __fsub_rn(cx, sx[i]);
        float dy = __fsub_rn(cy, sy[i]);
        float dz = __fsub_rn(cz, sz[i]);
        float d2 = __fadd_rn(__fadd_rn(__fmul_rn(dx,dx), __fmul_rn(dy,dy)), __fmul_rn(dz,dz));
        bool hit = d2 < R2;
        unsigned m = __ballot_sync(FULLMASK, hit);
        if (cnt == 0 && m) {
            int srcl = __ffs(m) - 1;
            fi = __shfl_sync(FULLMASK, i, srcl);
        }
        if (hit) {
            int r = cnt + __popc(m & ((1u << lane) - 1u));
            if (r < NSAMP) outp[r] = i;
        }
        cnt += __popc(m);
    }
    cnt = min(cnt, NSAMP);
    // pad with first found (center is always within radius -> cnt >= 1)
    if (lane >= cnt && lane < NSAMP) outp[lane] = fi;
}

// ---------------- GEMM helpers: 192 threads, tile 192 out x 64 cols, 8x8/thread ----------------
__global__ __launch_bounds__(192) void gemmB_kernel(const float* __restrict__ x) {
    __shared__ float Ws[KC][C2];
    __shared__ float Xs[KC][64];
    int b  = blockIdx.x >> 6;
    int n0 = (blockIdx.x & 63) * 64;
    int tid = threadIdx.x;
    int rt = tid >> 3, ct = tid & 7;
    float acc[8][8];
    #pragma unroll
    for (int i = 0; i < 8; i++)
        #pragma unroll
        for (int j = 0; j < 8; j++) acc[i][j] = 0.f;

    for (int kc = 0; kc < CC; kc += KC) {
        #pragma unroll
        for (int kk = 0; kk < KC; kk++)
            Ws[kk][tid] = d_WtT[(size_t)(CC + kc + kk)*C2 + tid];
        {
            int kk0 = tid / 64, nn = tid % 64;
            for (int kk = kk0; kk < KC; kk += 3)
                Xs[kk][nn] = fmaxf(x[((size_t)b*CC + kc + kk)*NN + n0 + nn], 0.f);
        }
        __syncthreads();
        #pragma unroll
        for (int kk = 0; kk < KC; kk++) {
            float wf[8], xf[8];
            #pragma unroll
            for (int i = 0; i < 8; i++) wf[i] = Ws[kk][rt*8 + i];
            #pragma unroll
            for (int i = 0; i < 8; i++) xf[i] = Xs[kk][ct*8 + i];
            #pragma unroll
            for (int i = 0; i < 8; i++)
                #pragma unroll
                for (int j = 0; j < 8; j++) acc[i][j] = fmaf(wf[i], xf[j], acc[i][j]);
        }
        __syncthreads();
    }
    float sc[8], sh[8];
    #pragma unroll
    for (int i = 0; i < 8; i++) { sc[i] = d_scale_t[rt*8+i]; sh[i] = d_shift_t[rt*8+i]; }
    #pragma unroll
    for (int j = 0; j < 8; j++) {
        int n = n0 + ct*8 + j;
        float* dst = d_Bfeat + ((size_t)(b*NN + n))*C2 + rt*8;
        #pragma unroll
        for (int i = 0; i < 8; i++) dst[i] = fmaf(sc[i], acc[i][j], sh[i]);
    }
}

__global__ __launch_bounds__(192) void gemmA_kernel(const float* __restrict__ x) {
    __shared__ float Ws[KC][C2];
    __shared__ float Xs[KC][64];
    __shared__ int sidx[64];
    int b  = blockIdx.x >> 4;
    int g0 = (blockIdx.x & 15) * 64;
    int tid = threadIdx.x;
    int rt = tid >> 3, ct = tid & 7;
    if (tid < 64) sidx[tid] = d_samp[b*NP + g0 + tid];
    __syncthreads();
    float acc[8][8];
    #pragma unroll
    for (int i = 0; i < 8; i++)
        #pragma unroll
        for (int j = 0; j < 8; j++) acc[i][j] = 0.f;

    for (int kc = 0; kc < CC; kc += KC) {
        #pragma unroll
        for (int kk = 0; kk < KC; kk++)
            Ws[kk][tid] = d_WtT[(size_t)(kc + kk)*C2 + tid];
        {
            int kk0 = tid / 64, nn = tid % 64;
            for (int kk = kk0; kk < KC; kk += 3)
                Xs[kk][nn] = fmaxf(x[((size_t)b*CC + kc + kk)*NN + sidx[nn]], 0.f);
        }
        __syncthreads();
        #pragma unroll
        for (int kk = 0; kk < KC; kk++) {
            float wf[8], xf[8];
            #pragma unroll
            for (int i = 0; i < 8; i++) wf[i] = Ws[kk][rt*8 + i];
            #pragma unroll
            for (int i = 0; i < 8; i++) xf[i] = Xs[kk][ct*8 + i];
            #pragma unroll
            for (int i = 0; i < 8; i++)
                #pragma unroll
                for (int j = 0; j < 8; j++) acc[i][j] = fmaf(wf[i], xf[j], acc[i][j]);
        }
        __syncthreads();
    }
    float sc[8];
    #pragma unroll
    for (int i = 0; i < 8; i++) sc[i] = d_scale_t[rt*8+i];
    #pragma unroll
    for (int j = 0; j < 8; j++) {
        int g = g0 + ct*8 + j;
        float* dst = d_Afeat + ((size_t)(b*NP + g))*C2 + rt*8;
        #pragma unroll
        for (int i = 0; i < 8; i++) dst[i] = sc[i] * acc[i][j];
    }
}

// ---------------- aggregation: one block (192 thr = channels) per center ----------------
__global__ __launch_bounds__(192) void agg_kernel(const float* __restrict__ p,
                                                  const float* __restrict__ newp) {
    int bg = blockIdx.x;           // b*1024 + g
    int b  = bg >> 10;
    int c  = threadIdx.x;
    __shared__ int   snbr[NSAMP];
    __shared__ float sctr[3];
    if (c < NSAMP) snbr[c] = d_nbr[(size_t)bg*NSAMP + c];
    if (c < 3)     sctr[c] = newp[(size_t)bg*3 + c];
    __syncthreads();

    float a = d_Afeat[(size_t)bg*C2 + c];
    int dim = c >> 6;
    int r = c & 63;
    bool isSin = r < 32;
    int j = isSin ? r : (r - 32);
    // 50 / 500^(j/32)
    float pm = 50.0f * exp2f(-(float)j * (8.965784284662087f / 32.0f));
    float ctr = sctr[dim];

    float vmax = -INFINITY, vsum = 0.f;
    #pragma unroll 4
    for (int s = 0; s < NSAMP; s++) {
        int ni = snbr[s];
        float bv = d_Bfeat[((size_t)(b*NN + ni))*C2 + c];
        float t = fmaxf(a + bv, 0.f);
        float dpd = p[((size_t)(b*NN + ni))*3 + dim] - ctr;
        float pos = dpd * pm;
        float e = isSin ? __sinf(pos) : __cosf(pos);
        float ag = fmaf(t, e, e);
        vmax = fmaxf(vmax, ag);
        vsum += ag;
    }
    float pooled = vmax + vsum * (1.0f / 16.0f);
    d_Pool[(size_t)bg*C2 + c] = fmaxf(pooled, 0.f);
}

// ---------------- final conv: 192x192 over 8192 cols ----------------
__global__ __launch_bounds__(192) void gemm2_kernel(float* __restrict__ out) {
    __shared__ float Ws[KC][C2];
    __shared__ float Xs[KC][64];
    int col0 = blockIdx.x * 64;        // global col in 0..8191 (= b*1024+g)
    int b  = col0 >> 10;
    int g0 = col0 & 1023;
    int tid = threadIdx.x;
    int rt = tid >> 3, ct = tid & 7;
    float acc[8][8];
    #pragma unroll
    for (int i = 0; i < 8; i++)
        #pragma unroll
        for (int j = 0; j < 8; j++) acc[i][j] = 0.f;

    for (int kc = 0; kc < C2; kc += KC) {
        #pragma unroll
        for (int kk = 0; kk < KC; kk++)
            Ws[kk][tid] = d_WcT[(size_t)(kc + kk)*C2 + tid];
        if (tid < 64) {
            const float4* src = (const float4*)(d_Pool + (size_t)(col0 + tid)*C2 + kc);
            #pragma unroll
            for (int q = 0; q < KC/4; q++) {
                float4 v = src[q];
                Xs[q*4+0][tid] = v.x;
                Xs[q*4+1][tid] = v.y;
                Xs[q*4+2][tid] = v.z;
                Xs[q*4+3][tid] = v.w;
            }
        }
        __syncthreads();
        #pragma unroll
        for (int kk = 0; kk < KC; kk++) {
            float wf[8], xf[8];
            #pragma unroll
            for (int i = 0; i < 8; i++) wf[i] = Ws[kk][rt*8 + i];
            #pragma unroll
            for (int i = 0; i < 8; i++) xf[i] = Xs[kk][ct*8 + i];
            #pragma unroll
            for (int i = 0; i < 8; i++)
                #pragma unroll
                for (int j = 0; j < 8; j++) acc[i][j] = fmaf(wf[i], xf[j], acc[i][j]);
        }
        __syncthreads();
    }
    float sc[8], sh[8];
    #pragma unroll
    for (int i = 0; i < 8; i++) { sc[i] = d_scale_c[rt*8+i]; sh[i] = d_shift_c[rt*8+i]; }
    #pragma unroll
    for (int i = 0; i < 8; i++) {
        int o = rt*8 + i;
        float* dst = out + (size_t)b*C2*NP + (size_t)o*NP + g0 + ct*8;
        #pragma unroll
        for (int j = 0; j < 8; j++) dst[j] = fmaxf(fmaf(sc[i], acc[i][j], sh[i]), 0.f);
    }
}

extern "C" void kernel_launch(void* const* d_in, const int* in_sizes, int n_in,
                              void* d_out, int out_size) {
    const float* p  = (const float*)d_in[0];
    const float* x  = (const float*)d_in[1];
    const float* Wt = (const float*)d_in[2];
    const float* gt = (const float*)d_in[3];
    const float* bt = (const float*)d_in[4];
    const float* mt = (const float*)d_in[5];
    const float* vt = (const float*)d_in[6];
    const float* Wc = (const float*)d_in[7];
    const float* gc = (const float*)d_in[8];
    const float* bc = (const float*)d_in[9];
    const float* mc = (const float*)d_in[10];
    const float* vc = (const float*)d_in[11];

    float* newp = (float*)d_out;                  // [8,1024,3]
    float* out  = (float*)d_out + BB*NP*3;        // [8,192,1024]

    prep_kernel<<<64, 256>>>(Wt, gt, bt, mt, vt, Wc, gc, bc, mc, vc);
    fps_kernel<<<BB, 1024>>>(p, newp);
    gemmB_kernel<<<BB*64, 192>>>(x);
    ballq_kernel<<<BB*64, 512>>>(p);
    gemmA_kernel<<<BB*16, 192>>>(x);
    agg_kernel<<<BB*NP, 192>>>(p, newp);
    gemm2_kernel<<<(BB*NP)/64, 192>>>(out);
}

// round 3
// speedup vs baseline: 1.6410x; 1.6410x over previous
#include <cuda_runtime.h>
#include <math.h>
#include <stdint.h>

#define BB 8
#define NN 4096
#define CC 96
#define C2 192
#define NP 1024
#define NSAMP 16
#define FULLMASK 0xffffffffu
#define KC 32

// ---- packed f32x2 helpers (exact per-lane IEEE RN, sm_103a) ----
#define MUL_F32X2(out, a, b) \
    asm("mul.rn.f32x2 %0, %1, %2;" : "=l"(out) : "l"(a), "l"(b))
#define ADD_F32X2(out, a, b) \
    asm("add.rn.f32x2 %0, %1, %2;" : "=l"(out) : "l"(a), "l"(b))
#define PACK_F32X2(out, lo, hi) \
    asm("mov.b64 %0, {%1, %2};" : "=l"(out) : "r"(lo), "r"(hi))
#define UNPACK_F32X2(lo, hi, in) \
    asm("mov.b64 {%0, %1}, %2;" : "=r"(lo), "=r"(hi) : "l"(in))

// ---------------- scratch ----------------
__device__ int   d_samp[BB*NP];
__device__ int   d_nbr[BB*NP*NSAMP];
__device__ float d_Bfeat[BB*NN*C2];    // [b][n][c]  = scale_t*(Wt[:,96:]@relu(x)) + shift_t
__device__ float d_Afeat[BB*NP*C2];    // [b][g][c]  = scale_t*(Wt[:,:96]@relu(x_samp))
__device__ float d_Pool[BB*NP*C2];     // [b][g][c]  = relu(max+mean pooled)
__device__ float d_WtT[C2*C2];         // [c][o]
__device__ float d_WcT[C2*C2];         // [c][o]
__device__ float d_scale_t[C2], d_shift_t[C2], d_scale_c[C2], d_shift_c[C2];

// ---------------- prep: transpose weights, fold BN ----------------
__global__ void prep_kernel(const float* __restrict__ Wt, const float* __restrict__ gt,
                            const float* __restrict__ bt, const float* __restrict__ mt,
                            const float* __restrict__ vt, const float* __restrict__ Wc,
                            const float* __restrict__ gc, const float* __restrict__ bc,
                            const float* __restrict__ mc, const float* __restrict__ vc) {
    int tid = threadIdx.x + blockIdx.x * blockDim.x;
    int stride = blockDim.x * gridDim.x;
    for (int i = tid; i < C2*C2; i += stride) {
        int o = i / C2, c = i % C2;
        d_WtT[c*C2 + o] = Wt[o*C2 + c];
        d_WcT[c*C2 + o] = Wc[o*C2 + c];
    }
    if (blockIdx.x == 0 && threadIdx.x < C2) {
        int i = threadIdx.x;
        float st = gt[i] / sqrtf(vt[i] + 1e-5f);
        d_scale_t[i] = st;
        d_shift_t[i] = bt[i] - mt[i]*st;
        float sc = gc[i] / sqrtf(vc[i] + 1e-5f);
        d_scale_c[i] = sc;
        d_shift_c[i] = bc[i] - mc[i]*sc;
    }
}

// ---------------- FPS: one block per batch; 1 barrier/iter, u64-key argmax ----------------
// Selection math is bit-exact vs reference: d = ((dx*dx + dy*dy) + dz*dz) in RN,
// sub done as add of negated operand (identical rounding). f32x2 ops are exact
// per-lane. Tie-break = smallest index via ~idx in the packed key.
__global__ __launch_bounds__(256, 1) void fps_kernel(const float* __restrict__ p,
                                                     float* __restrict__ newp) {
    extern __shared__ float smem[];
    float* sx = smem;
    float* sy = smem + NN;
    float* sz = smem + 2*NN;
    unsigned long long* skey = (unsigned long long*)(smem + 3*NN);  // [2][8]

    int b = blockIdx.x;
    const float* pb = p + (size_t)b * NN * 3;
    int tid = threadIdx.x, lane = tid & 31, warp = tid >> 5;

    for (int i = tid; i < NN; i += 256) {
        sx[i] = pb[3*i + 0];
        sy[i] = pb[3*i + 1];
        sz[i] = pb[3*i + 2];
    }
    __syncthreads();

    const int base = tid * 16;
    unsigned long long pxp[8], pyp[8], pzp[8];
    float mind[16];
    #pragma unroll
    for (int j = 0; j < 8; j++) {
        unsigned a, c;
        a = __float_as_uint(sx[base + 2*j]); c = __float_as_uint(sx[base + 2*j + 1]);
        PACK_F32X2(pxp[j], a, c);
        a = __float_as_uint(sy[base + 2*j]); c = __float_as_uint(sy[base + 2*j + 1]);
        PACK_F32X2(pyp[j], a, c);
        a = __float_as_uint(sz[base + 2*j]); c = __float_as_uint(sz[base + 2*j + 1]);
        PACK_F32X2(pzp[j], a, c);
    }
    #pragma unroll
    for (int i = 0; i < 16; i++) mind[i] = 1e10f;

    float lx = sx[0], ly = sy[0], lz = sz[0];
    if (tid == 0) {
        d_samp[b*NP + 0] = 0;
        newp[(size_t)(b*NP)*3 + 0] = lx;
        newp[(size_t)(b*NP)*3 + 1] = ly;
        newp[(size_t)(b*NP)*3 + 2] = lz;
    }

    for (int k = 1; k < NP; k++) {
        unsigned long long nlx, nly, nlz;
        {
            unsigned ax = __float_as_uint(-lx), ay = __float_as_uint(-ly), az = __float_as_uint(-lz);
            PACK_F32X2(nlx, ax, ax);
            PACK_F32X2(nly, ay, ay);
            PACK_F32X2(nlz, az, az);
        }
        #pragma unroll
        for (int j = 0; j < 8; j++) {
            unsigned long long dx, dy, dz, t1, t2, t3, s;
            ADD_F32X2(dx, pxp[j], nlx);
            ADD_F32X2(dy, pyp[j], nly);
            ADD_F32X2(dz, pzp[j], nlz);
            MUL_F32X2(t1, dx, dx);
            MUL_F32X2(t2, dy, dy);
            MUL_F32X2(t3, dz, dz);
            ADD_F32X2(s, t1, t2);
            ADD_F32X2(s, s, t3);
            unsigned lo, hi;
            UNPACK_F32X2(lo, hi, s);
            mind[2*j]   = fminf(mind[2*j],   __uint_as_float(lo));
            mind[2*j+1] = fminf(mind[2*j+1], __uint_as_float(hi));
        }
        // local argmax, first-occurrence tie-break
        float v = mind[0]; int ii = 0;
        #pragma unroll
        for (int i = 1; i < 16; i++) if (mind[i] > v) { v = mind[i]; ii = i; }
        unsigned long long key =
            ((unsigned long long)__float_as_uint(v) << 32) | (unsigned)(~(base + ii));
        #pragma unroll
        for (int o = 16; o; o >>= 1) {
            unsigned long long other = __shfl_xor_sync(FULLMASK, key, o);
            if (other > key) key = other;
        }
        int par = (k & 1) << 3;
        if (lane == 0) skey[par + warp] = key;
        __syncthreads();
        unsigned long long k2 = (lane < 8) ? skey[par + lane] : 0ull;
        #pragma unroll
        for (int o = 1; o <= 4; o <<= 1) {
            unsigned long long other = __shfl_xor_sync(FULLMASK, k2, o);
            if (other > k2) k2 = other;
        }
        k2 = __shfl_sync(FULLMASK, k2, 0);
        int scur = (int)(~(unsigned)k2);
        lx = sx[scur]; ly = sy[scur]; lz = sz[scur];
        if (tid == 0) {
            d_samp[b*NP + k] = scur;
            newp[(size_t)(b*NP + k)*3 + 0] = lx;
            newp[(size_t)(b*NP + k)*3 + 1] = ly;
            newp[(size_t)(b*NP + k)*3 + 2] = lz;
        }
    }
}

// ---------------- ball query: 16 warps/block, one warp per center ----------------
__global__ __launch_bounds__(512) void ballq_kernel(const float* __restrict__ p) {
    __shared__ float sx[NN], sy[NN], sz[NN];
    int b   = blockIdx.x >> 6;       // 64 groups per batch
    int grp = blockIdx.x & 63;
    const float* pb = p + (size_t)b * NN * 3;
    for (int i = threadIdx.x; i < NN; i += 512) {
        sx[i] = pb[3*i + 0];
        sy[i] = pb[3*i + 1];
        sz[i] = pb[3*i + 2];
    }
    __syncthreads();

    int warp = threadIdx.x >> 5, lane = threadIdx.x & 31;
    int g = grp*16 + warp;
    int cIdx = d_samp[b*NP + g];
    float cx = sx[cIdx], cy = sy[cIdx], cz = sz[cIdx];
    const float R2 = (float)(0.1 * 0.1);   // matches reference's f64->f32 rounding
    int* outp = d_nbr + ((size_t)(b*NP + g)) * NSAMP;

    int cnt = 0;
    int fi = 0;
    for (int basei = 0; basei < NN && cnt < NSAMP; basei += 32) {
        int i = basei + lane;
        float dx = __fsub_rn(cx, sx[i]);
        float dy = __fsub_rn(cy, sy[i]);
        float dz = __fsub_rn(cz, sz[i]);
        float d2 = __fadd_rn(__fadd_rn(__fmul_rn(dx,dx), __fmul_rn(dy,dy)), __fmul_rn(dz,dz));
        bool hit = d2 < R2;
        unsigned m = __ballot_sync(FULLMASK, hit);
        if (cnt == 0 && m) {
            int srcl = __ffs(m) - 1;
            fi = __shfl_sync(FULLMASK, i, srcl);
        }
        if (hit) {
            int r = cnt + __popc(m & ((1u << lane) - 1u));
            if (r < NSAMP) outp[r] = i;
        }
        cnt += __popc(m);
    }
    cnt = min(cnt, NSAMP);
    // pad with first found (center is always within radius -> cnt >= 1)
    if (lane >= cnt && lane < NSAMP) outp[lane] = fi;
}

// ---------------- GEMM helpers: 192 threads, tile 192 out x 64 cols, 8x8/thread ----------------
__global__ __launch_bounds__(192) void gemmB_kernel(const float* __restrict__ x) {
    __shared__ float Ws[KC][C2];
    __shared__ float Xs[KC][64];
    int b  = blockIdx.x >> 6;
    int n0 = (blockIdx.x & 63) * 64;
    int tid = threadIdx.x;
    int rt = tid >> 3, ct = tid & 7;
    float acc[8][8];
    #pragma unroll
    for (int i = 0; i < 8; i++)
        #pragma unroll
        for (int j = 0; j < 8; j++) acc[i][j] = 0.f;

    for (int kc = 0; kc < CC; kc += KC) {
        #pragma unroll
        for (int kk = 0; kk < KC; kk++)
            Ws[kk][tid] = d_WtT[(size_t)(CC + kc + kk)*C2 + tid];
        {
            int kk0 = tid / 64, nn = tid % 64;
            for (int kk = kk0; kk < KC; kk += 3)
                Xs[kk][nn] = fmaxf(x[((size_t)b*CC + kc + kk)*NN + n0 + nn], 0.f);
        }
        __syncthreads();
        #pragma unroll
        for (int kk = 0; kk < KC; kk++) {
            float wf[8], xf[8];
            #pragma unroll
            for (int i = 0; i < 8; i++) wf[i] = Ws[kk][rt*8 + i];
            #pragma unroll
            for (int i = 0; i < 8; i++) xf[i] = Xs[kk][ct*8 + i];
            #pragma unroll
            for (int i = 0; i < 8; i++)
                #pragma unroll
                for (int j = 0; j < 8; j++) acc[i][j] = fmaf(wf[i], xf[j], acc[i][j]);
        }
        __syncthreads();
    }
    float sc[8], sh[8];
    #pragma unroll
    for (int i = 0; i < 8; i++) { sc[i] = d_scale_t[rt*8+i]; sh[i] = d_shift_t[rt*8+i]; }
    #pragma unroll
    for (int j = 0; j < 8; j++) {
        int n = n0 + ct*8 + j;
        float* dst = d_Bfeat + ((size_t)(b*NN + n))*C2 + rt*8;
        #pragma unroll
        for (int i = 0; i < 8; i++) dst[i] = fmaf(sc[i], acc[i][j], sh[i]);
    }
}

__global__ __launch_bounds__(192) void gemmA_kernel(const float* __restrict__ x) {
    __shared__ float Ws[KC][C2];
    __shared__ float Xs[KC][64];
    __shared__ int sidx[64];
    int b  = blockIdx.x >> 4;
    int g0 = (blockIdx.x & 15) * 64;
    int tid = threadIdx.x;
    int rt = tid >> 3, ct = tid & 7;
    if (tid < 64) sidx[tid] = d_samp[b*NP + g0 + tid];
    __syncthreads();
    float acc[8][8];
    #pragma unroll
    for (int i = 0; i < 8; i++)
        #pragma unroll
        for (int j = 0; j < 8; j++) acc[i][j] = 0.f;

    for (int kc = 0; kc < CC; kc += KC) {
        #pragma unroll
        for (int kk = 0; kk < KC; kk++)
            Ws[kk][tid] = d_WtT[(size_t)(kc + kk)*C2 + tid];
        {
            int kk0 = tid / 64, nn = tid % 64;
            for (int kk = kk0; kk < KC; kk += 3)
                Xs[kk][nn] = fmaxf(x[((size_t)b*CC + kc + kk)*NN + sidx[nn]], 0.f);
        }
        __syncthreads();
        #pragma unroll
        for (int kk = 0; kk < KC; kk++) {
            float wf[8], xf[8];
            #pragma unroll
            for (int i = 0; i < 8; i++) wf[i] = Ws[kk][rt*8 + i];
            #pragma unroll
            for (int i = 0; i < 8; i++) xf[i] = Xs[kk][ct*8 + i];
            #pragma unroll
            for (int i = 0; i < 8; i++)
                #pragma unroll
                for (int j = 0; j < 8; j++) acc[i][j] = fmaf(wf[i], xf[j], acc[i][j]);
        }
        __syncthreads();
    }
    float sc[8];
    #pragma unroll
    for (int i = 0; i < 8; i++) sc[i] = d_scale_t[rt*8+i];
    #pragma unroll
    for (int j = 0; j < 8; j++) {
        int g = g0 + ct*8 + j;
        float* dst = d_Afeat + ((size_t)(b*NP + g))*C2 + rt*8;
        #pragma unroll
        for (int i = 0; i < 8; i++) dst[i] = sc[i] * acc[i][j];
    }
}

// ---------------- aggregation: one block (192 thr = channels) per center ----------------
__global__ __launch_bounds__(192) void agg_kernel(const float* __restrict__ p,
                                                  const float* __restrict__ newp) {
    int bg = blockIdx.x;           // b*1024 + g
    int b  = bg >> 10;
    int c  = threadIdx.x;
    __shared__ int   snbr[NSAMP];
    __shared__ float sctr[3];
    if (c < NSAMP) snbr[c] = d_nbr[(size_t)bg*NSAMP + c];
    if (c < 3)     sctr[c] = newp[(size_t)bg*3 + c];
    __syncthreads();

    float a = d_Afeat[(size_t)bg*C2 + c];
    int dim = c >> 6;
    int r = c & 63;
    bool isSin = r < 32;
    int j = isSin ? r : (r - 32);
    // 50 / 500^(j/32)
    float pm = 50.0f * exp2f(-(float)j * (8.965784284662087f / 32.0f));
    float ctr = sctr[dim];

    float vmax = -INFINITY, vsum = 0.f;
    #pragma unroll 4
    for (int s = 0; s < NSAMP; s++) {
        int ni = snbr[s];
        float bv = d_Bfeat[((size_t)(b*NN + ni))*C2 + c];
        float t = fmaxf(a + bv, 0.f);
        float dpd = p[((size_t)(b*NN + ni))*3 + dim] - ctr;
        float pos = dpd * pm;
        float e = isSin ? __sinf(pos) : __cosf(pos);
        float ag = fmaf(t, e, e);
        vmax = fmaxf(vmax, ag);
        vsum += ag;
    }
    float pooled = vmax + vsum * (1.0f / 16.0f);
    d_Pool[(size_t)bg*C2 + c] = fmaxf(pooled, 0.f);
}

// ---------------- final conv: 192x192 over 8192 cols ----------------
__global__ __launch_bounds__(192) void gemm2_kernel(float* __restrict__ out) {
    __shared__ float Ws[KC][C2];
    __shared__ float Xs[KC][64];
    int col0 = blockIdx.x * 64;        // global col in 0..8191 (= b*1024+g)
    int b  = col0 >> 10;
    int g0 = col0 & 1023;
    int tid = threadIdx.x;
    int rt = tid >> 3, ct = tid & 7;
    float acc[8][8];
    #pragma unroll
    for (int i = 0; i < 8; i++)
        #pragma unroll
        for (int j = 0; j < 8; j++) acc[i][j] = 0.f;

    for (int kc = 0; kc < C2; kc += KC) {
        #pragma unroll
        for (int kk = 0; kk < KC; kk++)
            Ws[kk][tid] = d_WcT[(size_t)(kc + kk)*C2 + tid];
        if (tid < 64) {
            const float4* src = (const float4*)(d_Pool + (size_t)(col0 + tid)*C2 + kc);
            #pragma unroll
            for (int q = 0; q < KC/4; q++) {
                float4 v = src[q];
                Xs[q*4+0][tid] = v.x;
                Xs[q*4+1][tid] = v.y;
                Xs[q*4+2][tid] = v.z;
                Xs[q*4+3][tid] = v.w;
            }
        }
        __syncthreads();
        #pragma unroll
        for (int kk = 0; kk < KC; kk++) {
            float wf[8], xf[8];
            #pragma unroll
            for (int i = 0; i < 8; i++) wf[i] = Ws[kk][rt*8 + i];
            #pragma unroll
            for (int i = 0; i < 8; i++) xf[i] = Xs[kk][ct*8 + i];
            #pragma unroll
            for (int i = 0; i < 8; i++)
                #pragma unroll
                for (int j = 0; j < 8; j++) acc[i][j] = fmaf(wf[i], xf[j], acc[i][j]);
        }
        __syncthreads();
    }
    float sc[8], sh[8];
    #pragma unroll
    for (int i = 0; i < 8; i++) { sc[i] = d_scale_c[rt*8+i]; sh[i] = d_shift_c[rt*8+i]; }
    #pragma unroll
    for (int i = 0; i < 8; i++) {
        int o = rt*8 + i;
        float* dst = out + (size_t)b*C2*NP + (size_t)o*NP + g0 + ct*8;
        #pragma unroll
        for (int j = 0; j < 8; j++) dst[j] = fmaxf(fmaf(sc[i], acc[i][j], sh[i]), 0.f);
    }
}

extern "C" void kernel_launch(void* const* d_in, const int* in_sizes, int n_in,
                              void* d_out, int out_size) {
    const float* p  = (const float*)d_in[0];
    const float* x  = (const float*)d_in[1];
    const float* Wt = (const float*)d_in[2];
    const float* gt = (const float*)d_in[3];
    const float* bt = (const float*)d_in[4];
    const float* mt = (const float*)d_in[5];
    const float* vt = (const float*)d_in[6];
    const float* Wc = (const float*)d_in[7];
    const float* gc = (const float*)d_in[8];
    const float* bc = (const float*)d_in[9];
    const float* mc = (const float*)d_in[10];
    const float* vc = (const float*)d_in[11];

    float* newp = (float*)d_out;                  // [8,1024,3]
    float* out  = (float*)d_out + BB*NP*3;        // [8,192,1024]

    // FPS dynamic smem: 3*4096 floats + 16 u64 keys
    const int FPS_SMEM = 3*NN*(int)sizeof(float) + 16*(int)sizeof(unsigned long long);
    cudaFuncSetAttribute(fps_kernel, cudaFuncAttributeMaxDynamicSharedMemorySize, FPS_SMEM);

    prep_kernel<<<64, 256>>>(Wt, gt, bt, mt, vt, Wc, gc, bc, mc, vc);
    fps_kernel<<<BB, 256, FPS_SMEM>>>(p, newp);
    gemmB_kernel<<<BB*64, 192>>>(x);
    ballq_kernel<<<BB*64, 512>>>(p);
    gemmA_kernel<<<BB*16, 192>>>(x);
    agg_kernel<<<BB*NP, 192>>>(p, newp);
    gemm2_kernel<<<(BB*NP)/64, 192>>>(out);
}

// round 4
// speedup vs baseline: 2.1619x; 1.3174x over previous
#include <cuda_runtime.h>
#include <math.h>
#include <stdint.h>

#define BB 8
#define NN 4096
#define CC 96
#define C2 192
#define NP 1024
#define NSAMP 16
#define FULLMASK 0xffffffffu
#define KC 32

// ---- packed f32x2 helpers (exact per-lane IEEE RN, sm_103a) ----
#define MUL_F32X2(out, a, b) \
    asm("mul.rn.f32x2 %0, %1, %2;" : "=l"(out) : "l"(a), "l"(b))
#define ADD_F32X2(out, a, b) \
    asm("add.rn.f32x2 %0, %1, %2;" : "=l"(out) : "l"(a), "l"(b))
#define PACK_F32X2(out, lo, hi) \
    asm("mov.b64 %0, {%1, %2};" : "=l"(out) : "r"(lo), "r"(hi))
#define UNPACK_F32X2(lo, hi, in) \
    asm("mov.b64 {%0, %1}, %2;" : "=r"(lo), "=r"(hi) : "l"(in))

// ---------------- scratch ----------------
__device__ int   d_samp[BB*NP];
__device__ int   d_nbr[BB*NP*NSAMP];
__device__ float d_Bfeat[BB*NN*C2];    // [b][n][c]
__device__ float d_Afeat[BB*NP*C2];    // [b][g][c]
__device__ float d_Pool[BB*NP*C2];     // [b][g][c]
__device__ int   d_cellStart[BB][1001];
__device__ int   d_cellPts[BB][NN];

// cell id, identical formula for build & query. Width 1/9.99 > 0.1 + rounding
// so any point within radius 0.1 of a center is in the center's 3x3x3 cell nbhd.
__device__ __forceinline__ int cellof(float x, float y, float z) {
    int ix = min(9, max(0, (int)(x * 9.99f)));
    int iy = min(9, max(0, (int)(y * 9.99f)));
    int iz = min(9, max(0, (int)(z * 9.99f)));
    return (ix * 10 + iy) * 10 + iz;
}

// ---------------- FPS body: 1 block per batch, REDUX-based argmax ----------------
__device__ __forceinline__ void fps_body(char* smraw, const float* __restrict__ p,
                                         float* __restrict__ newp, int b) {
    float* sx = (float*)smraw;
    float* sy = sx + NN;
    float* sz = sy + NN;
    unsigned* sred = (unsigned*)(sz + NN);   // [0..15]=vals(2 par), [16..31]=idx

    int tid = threadIdx.x, lane = tid & 31, warp = tid >> 5;
    const float* pb = p + (size_t)b * NN * 3;

    for (int i = tid; i < NN; i += 256) {
        sx[i] = pb[3*i + 0];
        sy[i] = pb[3*i + 1];
        sz[i] = pb[3*i + 2];
    }
    __syncthreads();

    const int base = tid * 16;
    unsigned long long pxp[8], pyp[8], pzp[8];
    float mind[16];
    #pragma unroll
    for (int j = 0; j < 8; j++) {
        unsigned a, c;
        a = __float_as_uint(sx[base + 2*j]); c = __float_as_uint(sx[base + 2*j + 1]);
        PACK_F32X2(pxp[j], a, c);
        a = __float_as_uint(sy[base + 2*j]); c = __float_as_uint(sy[base + 2*j + 1]);
        PACK_F32X2(pyp[j], a, c);
        a = __float_as_uint(sz[base + 2*j]); c = __float_as_uint(sz[base + 2*j + 1]);
        PACK_F32X2(pzp[j], a, c);
    }
    #pragma unroll
    for (int i = 0; i < 16; i++) mind[i] = 1e10f;

    float lx = sx[0], ly = sy[0], lz = sz[0];
    if (tid == 0) {
        d_samp[b*NP + 0] = 0;
        newp[(size_t)(b*NP)*3 + 0] = lx;
        newp[(size_t)(b*NP)*3 + 1] = ly;
        newp[(size_t)(b*NP)*3 + 2] = lz;
    }

    for (int k = 1; k < NP; k++) {
        unsigned long long nlx, nly, nlz;
        {
            unsigned ax = __float_as_uint(-lx), ay = __float_as_uint(-ly), az = __float_as_uint(-lz);
            PACK_F32X2(nlx, ax, ax);
            PACK_F32X2(nly, ay, ay);
            PACK_F32X2(nlz, az, az);
        }
        #pragma unroll
        for (int j = 0; j < 8; j++) {
            unsigned long long dx, dy, dz, t1, t2, t3, s;
            ADD_F32X2(dx, pxp[j], nlx);
            ADD_F32X2(dy, pyp[j], nly);
            ADD_F32X2(dz, pzp[j], nlz);
            MUL_F32X2(t1, dx, dx);
            MUL_F32X2(t2, dy, dy);
            MUL_F32X2(t3, dz, dz);
            ADD_F32X2(s, t1, t2);
            ADD_F32X2(s, s, t3);
            unsigned lo, hi;
            UNPACK_F32X2(lo, hi, s);
            mind[2*j]   = fminf(mind[2*j],   __uint_as_float(lo));
            mind[2*j+1] = fminf(mind[2*j+1], __uint_as_float(hi));
        }
        // local argmax over 16, tree, first-occurrence tie-break (a wins ties)
        float va[8]; int ia[8];
        #pragma unroll
        for (int j = 0; j < 8; j++) {
            float a = mind[2*j], c = mind[2*j+1];
            bool g = c > a;
            va[j] = g ? c : a;
            ia[j] = g ? (2*j+1) : (2*j);
        }
        float vb2[4]; int ib2[4];
        #pragma unroll
        for (int j = 0; j < 4; j++) {
            bool g = va[2*j+1] > va[2*j];
            vb2[j] = g ? va[2*j+1] : va[2*j];
            ib2[j] = g ? ia[2*j+1] : ia[2*j];
        }
        float vc2[2]; int ic2[2];
        #pragma unroll
        for (int j = 0; j < 2; j++) {
            bool g = vb2[2*j+1] > vb2[2*j];
            vc2[j] = g ? vb2[2*j+1] : vb2[2*j];
            ic2[j] = g ? ib2[2*j+1] : ib2[2*j];
        }
        bool gg = vc2[1] > vc2[0];
        float v = gg ? vc2[1] : vc2[0];
        int ii = gg ? ic2[1] : ic2[0];

        // warp reduce: distances >= 0 so uint order on bits == float order
        unsigned hib = __float_as_uint(v);
        unsigned m = __reduce_max_sync(FULLMASK, hib);
        unsigned cand = (hib == m) ? (unsigned)(base + ii) : 0xffffffffu;
        unsigned l = __reduce_min_sync(FULLMASK, cand);

        int par = (k & 1) << 3;
        if (lane == 0) { sred[par + warp] = m; sred[16 + par + warp] = l; }
        __syncthreads();
        unsigned v8 = (lane < 8) ? sred[par + lane] : 0u;
        unsigned bm = __reduce_max_sync(FULLMASK, v8);
        unsigned i8 = (lane < 8 && v8 == bm) ? sred[16 + par + lane] : 0xffffffffu;
        unsigned scur = __reduce_min_sync(FULLMASK, i8);

        lx = sx[scur]; ly = sy[scur]; lz = sz[scur];
        if (tid == 0) {
            d_samp[b*NP + k] = (int)scur;
            newp[(size_t)(b*NP + k)*3 + 0] = lx;
            newp[(size_t)(b*NP + k)*3 + 1] = ly;
            newp[(size_t)(b*NP + k)*3 + 2] = lz;
        }
    }
}

// ---------------- grid build body: 1 block per batch ----------------
__device__ __forceinline__ void gridbuild_body(char* smraw, const float* __restrict__ p, int b) {
    int* a  = (int*)smraw;        // 1024
    int* bb = a + 1024;           // 1024
    int tid = threadIdx.x;
    const float* pb = p + (size_t)b * NN * 3;

    for (int i = tid; i < 1024; i += 256) a[i] = 0;
    __syncthreads();

    int mycell[16];
    #pragma unroll
    for (int e = 0; e < 16; e++) {
        int i = e*256 + tid;
        int c = cellof(pb[3*i], pb[3*i+1], pb[3*i+2]);
        mycell[e] = c;
        atomicAdd(&a[c], 1);
    }
    __syncthreads();

    // inclusive scan over 1024 (Hillis-Steele, ping-pong)
    int* src = a; int* dst = bb;
    for (int off = 1; off < 1024; off <<= 1) {
        for (int i = tid; i < 1024; i += 256)
            dst[i] = src[i] + ((i >= off) ? src[i - off] : 0);
        __syncthreads();
        int* t = src; src = dst; dst = t;
    }
    // src holds inclusive scan. exclusive(i) = i ? src[i-1] : 0
    for (int i = tid; i <= 1000; i += 256)
        d_cellStart[b][i] = (i == 0) ? 0 : src[i-1];
    for (int i = tid; i < 1000; i += 256)
        dst[i] = (i == 0) ? 0 : src[i-1];       // cursors
    __syncthreads();

    #pragma unroll
    for (int e = 0; e < 16; e++) {
        int i = e*256 + tid;
        int slot = atomicAdd(&dst[mycell[e]], 1);
        d_cellPts[b][slot] = i;
    }
}

// ---------------- gemmB body: 256 thr, tile 192x64, thread tile 6x8 ----------------
__device__ __forceinline__ void gemmB_body(char* smraw, const float* __restrict__ x,
                                           const float* __restrict__ Wt,
                                           const float* __restrict__ gt, const float* __restrict__ bt,
                                           const float* __restrict__ mt, const float* __restrict__ vt,
                                           int rb) {
    float (*Ws)[C2] = (float (*)[C2])smraw;                 // [32][192]
    float (*Xs)[64] = (float (*)[64])(smraw + KC*C2*4);     // [32][64]
    float* ssc = (float*)(smraw + KC*C2*4 + KC*64*4);       // [192]
    float* ssh = ssc + C2;

    int tid = threadIdx.x;
    int b = rb >> 6, n0 = (rb & 63) * 64;
    if (tid < C2) {
        float st = gt[tid] / sqrtf(vt[tid] + 1e-5f);
        ssc[tid] = st;
        ssh[tid] = bt[tid] - mt[tid]*st;
    }
    int rt = tid >> 3, ct = tid & 7;       // rows rt*6.., cols ct*8..
    float acc[6][8];
    #pragma unroll
    for (int i = 0; i < 6; i++)
        #pragma unroll
        for (int j = 0; j < 8; j++) acc[i][j] = 0.f;

    for (int kc = 0; kc < CC; kc += KC) {
        if (tid < C2) {
            const float4* wr = (const float4*)(Wt + (size_t)tid*C2 + CC + kc);
            #pragma unroll
            for (int q = 0; q < 8; q++) {
                float4 w = wr[q];
                Ws[q*4+0][tid] = w.x; Ws[q*4+1][tid] = w.y;
                Ws[q*4+2][tid] = w.z; Ws[q*4+3][tid] = w.w;
            }
        }
        #pragma unroll
        for (int e = 0; e < 8; e++) {
            int idx = e*256 + tid;
            int kk = idx >> 6, nn = idx & 63;
            Xs[kk][nn] = fmaxf(x[((size_t)b*CC + kc + kk)*NN + n0 + nn], 0.f);
        }
        __syncthreads();
        #pragma unroll
        for (int kk = 0; kk < KC; kk++) {
            float wf[6], xf[8];
            const float2* wp = (const float2*)&Ws[kk][rt*6];
            float2 w0 = wp[0], w1 = wp[1], w2 = wp[2];
            wf[0]=w0.x; wf[1]=w0.y; wf[2]=w1.x; wf[3]=w1.y; wf[4]=w2.x; wf[5]=w2.y;
            const float4* xp = (const float4*)&Xs[kk][ct*8];
            float4 x0 = xp[0], x1 = xp[1];
            xf[0]=x0.x; xf[1]=x0.y; xf[2]=x0.z; xf[3]=x0.w;
            xf[4]=x1.x; xf[5]=x1.y; xf[6]=x1.z; xf[7]=x1.w;
            #pragma unroll
            for (int i = 0; i < 6; i++)
                #pragma unroll
                for (int j = 0; j < 8; j++) acc[i][j] = fmaf(wf[i], xf[j], acc[i][j]);
        }
        __syncthreads();
    }
    #pragma unroll
    for (int j = 0; j < 8; j++) {
        int n = n0 + ct*8 + j;
        float* dst = d_Bfeat + ((size_t)(b*NN + n))*C2 + rt*6;
        #pragma unroll
        for (int i = 0; i < 6; i++)
            dst[i] = fmaf(ssc[rt*6+i], acc[i][j], ssh[rt*6+i]);
    }
}

// ---------------- fused: blocks 0-7 FPS, 8-15 grid build, 16-527 gemmB ----------------
__global__ __launch_bounds__(256, 2) void fused1(const float* __restrict__ p,
                                                 const float* __restrict__ x,
                                                 const float* __restrict__ Wt,
                                                 const float* __restrict__ gt,
                                                 const float* __restrict__ bt,
                                                 const float* __restrict__ mt,
                                                 const float* __restrict__ vt,
                                                 float* __restrict__ newp) {
    extern __shared__ char sm[];
    int bid = blockIdx.x;
    if (bid < 8)       fps_body(sm, p, newp, bid);
    else if (bid < 16) gridbuild_body(sm, p, bid - 8);
    else               gemmB_body(sm, x, Wt, gt, bt, mt, vt, bid - 16);
}

// ---------------- ball query via grid: 1 warp per center ----------------
// Output = the 16 smallest in-radius indices (multiset; order-free since pooling
// is permutation-invariant), padded with the smallest hit when count < 16.
__global__ __launch_bounds__(256) void ballq_grid(const float* __restrict__ p) {
    __shared__ unsigned short lists[8][256];
    int warp = threadIdx.x >> 5, lane = threadIdx.x & 31;
    int gc = blockIdx.x * 8 + warp;       // b*1024 + g
    int b = gc >> 10;
    int cIdx = d_samp[gc];
    const float* pb = p + (size_t)b * NN * 3;
    float cx = pb[3*cIdx], cy = pb[3*cIdx+1], cz = pb[3*cIdx+2];
    int ccx = min(9, max(0, (int)(cx * 9.99f)));
    int ccy = min(9, max(0, (int)(cy * 9.99f)));
    int ccz = min(9, max(0, (int)(cz * 9.99f)));
    const float R2 = (float)(0.1 * 0.1);
    unsigned short* lst = lists[warp];
    const int* cs = d_cellStart[b];
    int hcnt = 0;

    int ix1 = min(9, ccx+1), iy1 = min(9, ccy+1), iz1 = min(9, ccz+1);
    for (int ix = max(0, ccx-1); ix <= ix1; ix++)
    for (int iy = max(0, ccy-1); iy <= iy1; iy++)
    for (int iz = max(0, ccz-1); iz <= iz1; iz++) {
        int cell = (ix*10 + iy)*10 + iz;
        int s = cs[cell], e = cs[cell + 1];
        for (int ob = s; ob < e; ob += 32) {
            int o = ob + lane;
            bool valid = o < e;
            int pid = valid ? d_cellPts[b][o] : 0;
            float dx = __fsub_rn(cx, pb[3*pid+0]);
            float dy = __fsub_rn(cy, pb[3*pid+1]);
            float dz = __fsub_rn(cz, pb[3*pid+2]);
            float d2 = __fadd_rn(__fadd_rn(__fmul_rn(dx,dx), __fmul_rn(dy,dy)), __fmul_rn(dz,dz));
            bool hit = valid && (d2 < R2);
            unsigned mb = __ballot_sync(FULLMASK, hit);
            if (hit) {
                int ps = hcnt + __popc(mb & ((1u << lane) - 1u));
                if (ps < 256) lst[ps] = (unsigned short)pid;
            }
            hcnt += __popc(mb);
        }
    }
    __syncwarp();
    int hs = min(hcnt, 256);
    int* outp = d_nbr + (size_t)gc * NSAMP;
    if (hs <= 32) {
        unsigned rv = (lane < hs) ? (unsigned)lst[lane] : 0xffffffffu;
        unsigned first = 0;
        #pragma unroll
        for (int r = 0; r < NSAMP; r++) {
            unsigned best = __reduce_min_sync(FULLMASK, rv);
            if (r == 0) first = best;
            if (lane == r) outp[r] = (int)((r < hs) ? best : first);
            if (rv == best) rv = 0xffffffffu;
        }
    } else {
        for (int r = 0; r < NSAMP; r++) {
            unsigned lm = 0xffffffffu;
            for (int j = lane; j < hs; j += 32) lm = min(lm, (unsigned)lst[j]);
            unsigned best = __reduce_min_sync(FULLMASK, lm);
            if (lane == r) outp[r] = (int)best;     // hs > 32 > r always valid
            for (int j = lane; j < hs; j += 32) if (lst[j] == best) lst[j] = 0xffff;
            __syncwarp();
        }
    }
}

// ---------------- gemmA: 192 thr, tile 192x64, 8x8/thread ----------------
__global__ __launch_bounds__(192) void gemmA_kernel(const float* __restrict__ x,
                                                    const float* __restrict__ Wt,
                                                    const float* __restrict__ gt,
                                                    const float* __restrict__ vt) {
    __shared__ float Ws[KC][C2];
    __shared__ float Xs[KC][64];
    __shared__ int sidx[64];
    __shared__ float ssc[C2];
    int b  = blockIdx.x >> 4;
    int g0 = (blockIdx.x & 15) * 64;
    int tid = threadIdx.x;
    int rt = tid >> 3, ct = tid & 7;
    if (tid < 64) sidx[tid] = d_samp[b*NP + g0 + tid];
    ssc[tid] = gt[tid] / sqrtf(vt[tid] + 1e-5f);
    float acc[8][8];
    #pragma unroll
    for (int i = 0; i < 8; i++)
        #pragma unroll
        for (int j = 0; j < 8; j++) acc[i][j] = 0.f;

    for (int kc = 0; kc < CC; kc += KC) {
        {
            const float4* wr = (const float4*)(Wt + (size_t)tid*C2 + kc);
            #pragma unroll
            for (int q = 0; q < 8; q++) {
                float4 w = wr[q];
                Ws[q*4+0][tid] = w.x; Ws[q*4+1][tid] = w.y;
                Ws[q*4+2][tid] = w.z; Ws[q*4+3][tid] = w.w;
            }
        }
        __syncthreads();
        {
            int kk0 = tid / 64, nn = tid % 64;
            for (int kk = kk0; kk < KC; kk += 3)
                Xs[kk][nn] = fmaxf(x[((size_t)b*CC + kc + kk)*NN + sidx[nn]], 0.f);
        }
        __syncthreads();
        #pragma unroll
        for (int kk = 0; kk < KC; kk++) {
            float wf[8], xf[8];
            #pragma unroll
            for (int i = 0; i < 8; i++) wf[i] = Ws[kk][rt*8 + i];
            #pragma unroll
            for (int i = 0; i < 8; i++) xf[i] = Xs[kk][ct*8 + i];
            #pragma unroll
            for (int i = 0; i < 8; i++)
                #pragma unroll
                for (int j = 0; j < 8; j++) acc[i][j] = fmaf(wf[i], xf[j], acc[i][j]);
        }
        __syncthreads();
    }
    #pragma unroll
    for (int j = 0; j < 8; j++) {
        int g = g0 + ct*8 + j;
        float* dst = d_Afeat + ((size_t)(b*NP + g))*C2 + rt*8;
        #pragma unroll
        for (int i = 0; i < 8; i++) dst[i] = ssc[rt*8+i] * acc[i][j];
    }
}

// ---------------- aggregation: one block (192 thr = channels) per center ----------------
__global__ __launch_bounds__(192) void agg_kernel(const float* __restrict__ p,
                                                  const float* __restrict__ newp) {
    int bg = blockIdx.x;           // b*1024 + g
    int b  = bg >> 10;
    int c  = threadIdx.x;
    __shared__ int   snbr[NSAMP];
    __shared__ float sctr[3];
    if (c < NSAMP) snbr[c] = d_nbr[(size_t)bg*NSAMP + c];
    if (c < 3)     sctr[c] = newp[(size_t)bg*3 + c];
    __syncthreads();

    float a = d_Afeat[(size_t)bg*C2 + c];
    int dim = c >> 6;
    int r = c & 63;
    bool isSin = r < 32;
    int j = isSin ? r : (r - 32);
    float pm = 50.0f * exp2f(-(float)j * (8.965784284662087f / 32.0f));
    float ctr = sctr[dim];

    float vmax = -INFINITY, vsum = 0.f;
    #pragma unroll 4
    for (int s = 0; s < NSAMP; s++) {
        int ni = snbr[s];
        float bv = d_Bfeat[((size_t)(b*NN + ni))*C2 + c];
        float t = fmaxf(a + bv, 0.f);
        float dpd = p[((size_t)(b*NN + ni))*3 + dim] - ctr;
        float pos = dpd * pm;
        float e = isSin ? __sinf(pos) : __cosf(pos);
        float ag = fmaf(t, e, e);
        vmax = fmaxf(vmax, ag);
        vsum += ag;
    }
    float pooled = vmax + vsum * (1.0f / 16.0f);
    d_Pool[(size_t)bg*C2 + c] = fmaxf(pooled, 0.f);
}

// ---------------- final conv: 192x192 over 8192 cols ----------------
__global__ __launch_bounds__(192) void gemm2_kernel(const float* __restrict__ Wc,
                                                    const float* __restrict__ gc,
                                                    const float* __restrict__ bc,
                                                    const float* __restrict__ mc,
                                                    const float* __restrict__ vc,
                                                    float* __restrict__ out) {
    __shared__ float Ws[KC][C2];
    __shared__ float Xs[KC][64];
    __shared__ float ssc[C2], ssh[C2];
    int col0 = blockIdx.x * 64;
    int b  = col0 >> 10;
    int g0 = col0 & 1023;
    int tid = threadIdx.x;
    int rt = tid >> 3, ct = tid & 7;
    {
        float st = gc[tid] / sqrtf(vc[tid] + 1e-5f);
        ssc[tid] = st;
        ssh[tid] = bc[tid] - mc[tid]*st;
    }
    float acc[8][8];
    #pragma unroll
    for (int i = 0; i < 8; i++)
        #pragma unroll
        for (int j = 0; j < 8; j++) acc[i][j] = 0.f;

    for (int kc = 0; kc < C2; kc += KC) {
        {
            const float4* wr = (const float4*)(Wc + (size_t)tid*C2 + kc);
            #pragma unroll
            for (int q = 0; q < 8; q++) {
                float4 w = wr[q];
                Ws[q*4+0][tid] = w.x; Ws[q*4+1][tid] = w.y;
                Ws[q*4+2][tid] = w.z; Ws[q*4+3][tid] = w.w;
            }
        }
        if (tid < 64) {
            const float4* src = (const float4*)(d_Pool + (size_t)(col0 + tid)*C2 + kc);
            #pragma unroll
            for (int q = 0; q < KC/4; q++) {
                float4 v = src[q];
                Xs[q*4+0][tid] = v.x;
                Xs[q*4+1][tid] = v.y;
                Xs[q*4+2][tid] = v.z;
                Xs[q*4+3][tid] = v.w;
            }
        }
        __syncthreads();
        #pragma unroll
        for (int kk = 0; kk < KC; kk++) {
            float wf[8], xf[8];
            #pragma unroll
            for (int i = 0; i < 8; i++) wf[i] = Ws[kk][rt*8 + i];
            #pragma unroll
            for (int i = 0; i < 8; i++) xf[i] = Xs[kk][ct*8 + i];
            #pragma unroll
            for (int i = 0; i < 8; i++)
                #pragma unroll
                for (int j = 0; j < 8; j++) acc[i][j] = fmaf(wf[i], xf[j], acc[i][j]);
        }
        __syncthreads();
    }
    #pragma unroll
    for (int i = 0; i < 8; i++) {
        int o = rt*8 + i;
        float* dst = out + (size_t)b*C2*NP + (size_t)o*NP + g0 + ct*8;
        #pragma unroll
        for (int j = 0; j < 8; j++)
            dst[j] = fmaxf(fmaf(ssc[o], acc[i][j], ssh[o]), 0.f);
    }
}

extern "C" void kernel_launch(void* const* d_in, const int* in_sizes, int n_in,
                              void* d_out, int out_size) {
    const float* p  = (const float*)d_in[0];
    const float* x  = (const float*)d_in[1];
    const float* Wt = (const float*)d_in[2];
    const float* gt = (const float*)d_in[3];
    const float* bt = (const float*)d_in[4];
    const float* mt = (const float*)d_in[5];
    const float* vt = (const float*)d_in[6];
    const float* Wc = (const float*)d_in[7];
    const float* gc = (const float*)d_in[8];
    const float* bc = (const float*)d_in[9];
    const float* mc = (const float*)d_in[10];
    const float* vc = (const float*)d_in[11];

    float* newp = (float*)d_out;                  // [8,1024,3]
    float* out  = (float*)d_out + BB*NP*3;        // [8,192,1024]

    const int FUSED_SMEM = 3*NN*(int)sizeof(float) + 32*(int)sizeof(unsigned);  // 49280
    cudaFuncSetAttribute(fused1, cudaFuncAttributeMaxDynamicSharedMemorySize, FUSED_SMEM);

    fused1<<<16 + BB*64, 256, FUSED_SMEM>>>(p, x, Wt, gt, bt, mt, vt, newp);
    ballq_grid<<<BB*NP/8, 256>>>(p);
    gemmA_kernel<<<BB*16, 192>>>(x, Wt, gt, vt);
    agg_kernel<<<BB*NP, 192>>>(p, newp);
    gemm2_kernel<<<(BB*NP)/64, 192>>>(Wc, gc, bc, mc, vc, out);
}